// round 1
// baseline (speedup 1.0000x reference)
#include <cuda_runtime.h>
#include <cstdint>
#include <cstddef>

// Problem constants (fixed by the dataset)
#define NN 50000
#define EE 800000
// layer1: IN_C=256, heads=2, HID=128 -> h1: [N,256]
// layer2: in 256, heads=1, OUT=128   -> h2: [N,128]

// ---------------- device scratch (no allocs allowed) ----------------
__device__ float  g_h1[NN * 256];    // x @ W1
__device__ float  g_acc1[NN * 256];  // unnormalized aggregate, then ELU'd hidden
__device__ float  g_h2[NN * 128];    // hidden @ W2
__device__ float2 g_as1[NN], g_ad1[NN], g_m1[NN], g_den1[NN];
__device__ float  g_as2[NN], g_ad2[NN], g_m2[NN], g_den2[NN];

// ---------------- helpers ----------------
__device__ __forceinline__ float leaky(float x) { return x > 0.f ? x : 0.2f * x; }

__device__ __forceinline__ void atomicMaxF(float* addr, float value) {
  // ordered-int trick, valid for mixed signs, no NaNs in this workload
  if (value >= 0.f)
    atomicMax((int*)addr, __float_as_int(value));
  else
    atomicMin((unsigned int*)addr, __float_as_uint(value));
}

__device__ __forceinline__ void red_add_v4(float* addr, float4 v) {
  asm volatile("red.global.add.v4.f32 [%0], {%1, %2, %3, %4};"
               :: "l"(addr), "f"(v.x), "f"(v.y), "f"(v.z), "f"(v.w)
               : "memory");
}

// ---------------- SGEMM: C[M,N] = A[M,K] @ B[K,N] ----------------
__global__ __launch_bounds__(256) void sgemm_kernel(
    const float* __restrict__ A, const float* __restrict__ B,
    float* __restrict__ C, int M, int N, int K) {
  constexpr int BM = 128, BN = 128, BK = 16, TM = 8, TN = 8;
  __shared__ float As[BK][BM];
  __shared__ float Bs[BK][BN];
  int tid = threadIdx.x;
  int bm = blockIdx.y * BM;
  int bn = blockIdx.x * BN;
  int tx = tid & 15, ty = tid >> 4;
  float acc[TM][TN] = {};
  for (int k0 = 0; k0 < K; k0 += BK) {
#pragma unroll
    for (int i = 0; i < 2; ++i) {  // A tile: 128x16, 512 float4 / 256 thr
      int idx = tid + i * 256;
      int r = idx >> 2;
      int c4 = (idx & 3) * 4;
      float4 v = make_float4(0.f, 0.f, 0.f, 0.f);
      int grow = bm + r;
      if (grow < M) v = *(const float4*)(A + (size_t)grow * K + k0 + c4);
      As[c4 + 0][r] = v.x; As[c4 + 1][r] = v.y;
      As[c4 + 2][r] = v.z; As[c4 + 3][r] = v.w;
    }
#pragma unroll
    for (int i = 0; i < 2; ++i) {  // B tile: 16x128
      int idx = tid + i * 256;
      int r = idx >> 5;
      int c4 = (idx & 31) * 4;
      *(float4*)&Bs[r][c4] = *(const float4*)(B + (size_t)(k0 + r) * N + bn + c4);
    }
    __syncthreads();
#pragma unroll
    for (int k = 0; k < BK; ++k) {
      float a[TM], b[TN];
      *(float4*)&a[0] = *(float4*)&As[k][ty * TM];
      *(float4*)&a[4] = *(float4*)&As[k][ty * TM + 4];
      *(float4*)&b[0] = *(float4*)&Bs[k][tx * TN];
      *(float4*)&b[4] = *(float4*)&Bs[k][tx * TN + 4];
#pragma unroll
      for (int i = 0; i < TM; i++)
#pragma unroll
        for (int j = 0; j < TN; j++) acc[i][j] = fmaf(a[i], b[j], acc[i][j]);
    }
    __syncthreads();
  }
#pragma unroll
  for (int i = 0; i < TM; i++) {
    int grow = bm + ty * TM + i;
    if (grow < M) {
#pragma unroll
      for (int j = 0; j < TN; j += 4)
        *(float4*)(C + (size_t)grow * N + bn + tx * TN + j) = *(float4*)&acc[i][j];
    }
  }
}

// ---------------- layer 1 (2 heads of 128) ----------------

// per (node, head): attention dots + self-loop max init
__global__ void alpha1_kernel(int Nn, const float* __restrict__ a_s,
                              const float* __restrict__ a_d) {
  int gw = (blockIdx.x * blockDim.x + threadIdx.x) >> 5;
  int lane = threadIdx.x & 31;
  int n = gw >> 1, head = gw & 1;
  if (n >= Nn) return;
  const float* hp = g_h1 + (size_t)n * 256 + head * 128;
  const float* asp = a_s + head * 128;
  const float* adp = a_d + head * 128;
  float s = 0.f, d = 0.f;
#pragma unroll
  for (int c = lane; c < 128; c += 32) {
    float hv = hp[c];
    s = fmaf(hv, asp[c], s);
    d = fmaf(hv, adp[c], d);
  }
#pragma unroll
  for (int o = 16; o; o >>= 1) {
    s += __shfl_xor_sync(0xffffffffu, s, o);
    d += __shfl_xor_sync(0xffffffffu, d, o);
  }
  if (lane == 0) {
    ((float*)g_as1)[n * 2 + head] = s;
    ((float*)g_ad1)[n * 2 + head] = d;
    ((float*)g_m1)[n * 2 + head] = leaky(s + d);  // self-loop score init
  }
}

__global__ void edge_max1_kernel(const int* __restrict__ ei, int E) {
  int e = blockIdx.x * blockDim.x + threadIdx.x;
  if (e >= E) return;
  int s = __ldg(ei + e), d = __ldg(ei + E + e);
  float2 a = g_as1[s], b = g_ad1[d];
  atomicMaxF(&((float*)g_m1)[2 * d], leaky(a.x + b.x));
  atomicMaxF(&((float*)g_m1)[2 * d + 1], leaky(a.y + b.y));
}

// init denom + acc with the self-loop contribution
__global__ void init1_kernel(int Nn) {
  int idx = blockIdx.x * blockDim.x + threadIdx.x;  // one float4 each
  if (idx >= Nn * 64) return;
  int n = idx >> 6, c4 = idx & 63;
  float2 a = g_as1[n], b = g_ad1[n], mm = g_m1[n];
  float ex0 = __expf(leaky(a.x + b.x) - mm.x);
  float ex1 = __expf(leaky(a.y + b.y) - mm.y);
  if (c4 == 0) g_den1[n] = make_float2(ex0, ex1);
  float ex = (c4 >= 32) ? ex1 : ex0;
  float4 v = *((const float4*)g_h1 + (size_t)n * 64 + c4);
  v.x *= ex; v.y *= ex; v.z *= ex; v.w *= ex;
  *((float4*)g_acc1 + (size_t)n * 64 + c4) = v;
}

// one warp per edge: denom += ex ; acc[dst] += ex * h1[src]
__global__ void edge_acc1_kernel(const int* __restrict__ ei, int E) {
  int gw = (blockIdx.x * blockDim.x + threadIdx.x) >> 5;
  int lane = threadIdx.x & 31;
  if (gw >= E) return;
  int s = __ldg(ei + gw), d = __ldg(ei + E + gw);
  float2 a = g_as1[s], b = g_ad1[d], mm = g_m1[d];
  float ex0 = __expf(leaky(a.x + b.x) - mm.x);
  float ex1 = __expf(leaky(a.y + b.y) - mm.y);
  if (lane == 0) atomicAdd(&((float*)g_den1)[2 * d], ex0);
  if (lane == 1) atomicAdd(&((float*)g_den1)[2 * d + 1], ex1);
  const float4* hs = (const float4*)g_h1 + (size_t)s * 64;
  float* ac = g_acc1 + (size_t)d * 256;
#pragma unroll
  for (int i = 0; i < 2; ++i) {
    int c4 = i * 32 + lane;              // 0..63 ; head1 iff c4>=32
    float ex = (c4 >= 32) ? ex1 : ex0;
    float4 v = __ldg(hs + c4);
    v.x *= ex; v.y *= ex; v.z *= ex; v.w *= ex;
    red_add_v4(ac + c4 * 4, v);
  }
}

// normalize + bias + ELU, in place (becomes layer-2 input)
__global__ void fin1_kernel(int Nn, const float* __restrict__ b1) {
  int idx = blockIdx.x * blockDim.x + threadIdx.x;
  if (idx >= Nn * 64) return;
  int n = idx >> 6, c4 = idx & 63;
  float2 dd = g_den1[n];
  float ds = (c4 >= 32) ? dd.y : dd.x;
  float inv = 1.0f / ds;
  float4 v = *((float4*)g_acc1 + idx);
  float4 bb = __ldg((const float4*)b1 + c4);
  v.x = v.x * inv + bb.x; v.y = v.y * inv + bb.y;
  v.z = v.z * inv + bb.z; v.w = v.w * inv + bb.w;
  v.x = v.x > 0.f ? v.x : expm1f(v.x);
  v.y = v.y > 0.f ? v.y : expm1f(v.y);
  v.z = v.z > 0.f ? v.z : expm1f(v.z);
  v.w = v.w > 0.f ? v.w : expm1f(v.w);
  *((float4*)g_acc1 + idx) = v;
}

// ---------------- layer 2 (1 head of 128) ----------------

__global__ void alpha2_kernel(int Nn, const float* __restrict__ a_s,
                              const float* __restrict__ a_d) {
  int n = (blockIdx.x * blockDim.x + threadIdx.x) >> 5;
  int lane = threadIdx.x & 31;
  if (n >= Nn) return;
  const float* hp = g_h2 + (size_t)n * 128;
  float s = 0.f, d = 0.f;
#pragma unroll
  for (int c = lane; c < 128; c += 32) {
    float hv = hp[c];
    s = fmaf(hv, a_s[c], s);
    d = fmaf(hv, a_d[c], d);
  }
#pragma unroll
  for (int o = 16; o; o >>= 1) {
    s += __shfl_xor_sync(0xffffffffu, s, o);
    d += __shfl_xor_sync(0xffffffffu, d, o);
  }
  if (lane == 0) {
    g_as2[n] = s;
    g_ad2[n] = d;
    g_m2[n] = leaky(s + d);
  }
}

__global__ void edge_max2_kernel(const int* __restrict__ ei, int E) {
  int e = blockIdx.x * blockDim.x + threadIdx.x;
  if (e >= E) return;
  int s = __ldg(ei + e), d = __ldg(ei + E + e);
  atomicMaxF(&g_m2[d], leaky(g_as2[s] + g_ad2[d]));
}

__global__ void init2_kernel(int Nn, float* __restrict__ out) {
  int idx = blockIdx.x * blockDim.x + threadIdx.x;  // one float4 each
  if (idx >= Nn * 32) return;
  int n = idx >> 5, c4 = idx & 31;
  float ex = __expf(leaky(g_as2[n] + g_ad2[n]) - g_m2[n]);
  if (c4 == 0) g_den2[n] = ex;
  float4 v = *((const float4*)g_h2 + (size_t)n * 32 + c4);
  v.x *= ex; v.y *= ex; v.z *= ex; v.w *= ex;
  *((float4*)out + idx) = v;
}

__global__ void edge_acc2_kernel(const int* __restrict__ ei, int E,
                                 float* __restrict__ out) {
  int gw = (blockIdx.x * blockDim.x + threadIdx.x) >> 5;
  int lane = threadIdx.x & 31;
  if (gw >= E) return;
  int s = __ldg(ei + gw), d = __ldg(ei + E + gw);
  float ex = __expf(leaky(g_as2[s] + g_ad2[d]) - g_m2[d]);
  if (lane == 0) atomicAdd(&g_den2[d], ex);
  float4 v = __ldg((const float4*)g_h2 + (size_t)s * 32 + lane);
  v.x *= ex; v.y *= ex; v.z *= ex; v.w *= ex;
  red_add_v4(out + (size_t)d * 128 + lane * 4, v);
}

__global__ void fin2_kernel(int Nn, const float* __restrict__ b2,
                            float* __restrict__ out) {
  int idx = blockIdx.x * blockDim.x + threadIdx.x;
  if (idx >= Nn * 32) return;
  int n = idx >> 5, c4 = idx & 31;
  float inv = 1.0f / g_den2[n];
  float4 v = *((float4*)out + idx);
  float4 bb = __ldg((const float4*)b2 + c4);
  v.x = v.x * inv + bb.x; v.y = v.y * inv + bb.y;
  v.z = v.z * inv + bb.z; v.w = v.w * inv + bb.w;
  *((float4*)out + idx) = v;
}

// ---------------- host launcher ----------------
extern "C" void kernel_launch(void* const* d_in, const int* in_sizes, int n_in,
                              void* d_out, int out_size) {
  const float* x     = (const float*)d_in[0];
  const int*   ei    = (const int*)d_in[1];
  const float* W1    = (const float*)d_in[2];
  const float* a_s1  = (const float*)d_in[3];
  const float* a_d1  = (const float*)d_in[4];
  const float* b1    = (const float*)d_in[5];
  const float* W2    = (const float*)d_in[6];
  const float* a_s2  = (const float*)d_in[7];
  const float* a_d2  = (const float*)d_in[8];
  const float* b2    = (const float*)d_in[9];
  float* out = (float*)d_out;

  int Nn = in_sizes[0] / 256;
  int E  = in_sizes[1] / 2;

  float *p_h1, *p_acc1, *p_h2;
  cudaGetSymbolAddress((void**)&p_h1, g_h1);
  cudaGetSymbolAddress((void**)&p_acc1, g_acc1);
  cudaGetSymbolAddress((void**)&p_h2, g_h2);

  const int TB = 256;

  // ---- layer 1 ----
  {
    dim3 grid((256 + 127) / 128, (Nn + 127) / 128);
    sgemm_kernel<<<grid, TB>>>(x, W1, p_h1, Nn, 256, 256);
  }
  alpha1_kernel<<<(Nn * 2 * 32 + TB - 1) / TB, TB>>>(Nn, a_s1, a_d1);
  edge_max1_kernel<<<(E + TB - 1) / TB, TB>>>(ei, E);
  init1_kernel<<<(Nn * 64 + TB - 1) / TB, TB>>>(Nn);
  edge_acc1_kernel<<<(E * 32 + TB - 1) / TB, TB>>>(ei, E);
  fin1_kernel<<<(Nn * 64 + TB - 1) / TB, TB>>>(Nn, b1);

  // ---- layer 2 ----
  {
    dim3 grid((128 + 127) / 128, (Nn + 127) / 128);
    sgemm_kernel<<<grid, TB>>>(p_acc1, W2, p_h2, Nn, 128, 256);
  }
  alpha2_kernel<<<(Nn * 32 + TB - 1) / TB, TB>>>(Nn, a_s2, a_d2);
  edge_max2_kernel<<<(E + TB - 1) / TB, TB>>>(ei, E);
  init2_kernel<<<(Nn * 32 + TB - 1) / TB, TB>>>(Nn, out);
  edge_acc2_kernel<<<(E * 32 + TB - 1) / TB, TB>>>(ei, E, out);
  fin2_kernel<<<(Nn * 32 + TB - 1) / TB, TB>>>(Nn, b2, out);
}

// round 4
// speedup vs baseline: 1.3533x; 1.3533x over previous
#include <cuda_runtime.h>
#include <cuda_bf16.h>
#include <cstdint>
#include <cstddef>

// Problem constants (fixed by the dataset)
#define NN 50000
#define EE 800000
// layer1: IN_C=256, heads=2, HID=128 -> h1: [N,256]
// layer2: in 256, heads=1, OUT=128   -> h2: [N,128]

// ---------------- device scratch (no allocs allowed) ----------------
__device__ float  g_h1[NN * 256];    // x @ W1
__device__ float  g_acc1[NN * 256];  // unnormalized aggregate, then ELU'd hidden
__device__ float  g_h2[NN * 128];    // hidden @ W2
__device__ float2 g_as1[NN], g_ad1[NN], g_m1[NN], g_den1[NN];
__device__ float  g_as2[NN], g_ad2[NN], g_m2[NN], g_den2[NN];
// transposed + bf16-split weights: [N][K] K-major
__device__ __nv_bfloat16 g_w1t_hi[256 * 256], g_w1t_lo[256 * 256];
__device__ __nv_bfloat16 g_w2t_hi[128 * 256], g_w2t_lo[128 * 256];

// ---------------- misc helpers ----------------
__device__ __forceinline__ float leaky(float x) { return x > 0.f ? x : 0.2f * x; }

__device__ __forceinline__ void atomicMaxF(float* addr, float value) {
  if (value >= 0.f)
    atomicMax((int*)addr, __float_as_int(value));
  else
    atomicMin((unsigned int*)addr, __float_as_uint(value));
}

__device__ __forceinline__ void red_add_v4(float* addr, float4 v) {
  asm volatile("red.global.add.v4.f32 [%0], {%1, %2, %3, %4};"
               :: "l"(addr), "f"(v.x), "f"(v.y), "f"(v.z), "f"(v.w)
               : "memory");
}

__device__ __forceinline__ void mma16816(float* c, const uint32_t* a,
                                         const uint32_t* b) {
  asm volatile(
      "mma.sync.aligned.m16n8k16.row.col.f32.bf16.bf16.f32 "
      "{%0,%1,%2,%3}, {%4,%5,%6,%7}, {%8,%9}, {%0,%1,%2,%3};"
      : "+f"(c[0]), "+f"(c[1]), "+f"(c[2]), "+f"(c[3])
      : "r"(a[0]), "r"(a[1]), "r"(a[2]), "r"(a[3]), "r"(b[0]), "r"(b[1]));
}

// ---------------- weight prep: W[K,N] fp32 -> Wt hi/lo bf16 [N,K] ----------------
__global__ void wprep_kernel(const float* __restrict__ W, int K, int N,
                             __nv_bfloat16* __restrict__ hi,
                             __nv_bfloat16* __restrict__ lo) {
  int idx = blockIdx.x * blockDim.x + threadIdx.x;
  if (idx >= K * N) return;
  int k = idx / N, n = idx % N;
  float v = W[idx];
  __nv_bfloat16 h = __float2bfloat16_rn(v);
  hi[n * K + k] = h;
  lo[n * K + k] = __float2bfloat16_rn(v - __bfloat162float(h));
}

// ---------------- mma.sync GEMM: C[M,N] = A[M,256] @ Bt^T (BF16x3 split) ----------------
// Bt hi/lo: [N,256] bf16 K-major. CTA tile: 128(M) x 128(N). 8 warps @ 64x32.
// SMEM row stride 72 bf16 (64 data + 8 pad) -> conflict-free fragment loads.
#define SROW 72
__global__ __launch_bounds__(256) void gemm_mma_kernel(
    const float* __restrict__ A, const __nv_bfloat16* __restrict__ Bhi,
    const __nv_bfloat16* __restrict__ Blo, float* __restrict__ C, int M, int N) {
  constexpr int K = 256;
  extern __shared__ __nv_bfloat16 sm[];
  __nv_bfloat16* sAh = sm;
  __nv_bfloat16* sAl = sm + 128 * SROW;
  __nv_bfloat16* sBh = sm + 2 * 128 * SROW;
  __nv_bfloat16* sBl = sm + 3 * 128 * SROW;

  int tid = threadIdx.x, wid = tid >> 5, lane = tid & 31;
  int bm = blockIdx.y * 128, bn = blockIdx.x * 128;
  int wm = (wid >> 2) * 64, wn = (wid & 3) * 32;
  int lr = lane >> 2, lc = lane & 3;  // fragment row group / col group

  float acc[4][4][4];
#pragma unroll
  for (int i = 0; i < 4; i++)
#pragma unroll
    for (int j = 0; j < 4; j++)
#pragma unroll
      for (int q = 0; q < 4; q++) acc[i][j][q] = 0.f;

  for (int c = 0; c < 4; ++c) {
    int k0 = c * 64;
    // ---- A chunk: 128 rows x 64 fp32, split to hi/lo bf16 ----
#pragma unroll
    for (int i = 0; i < 8; ++i) {
      int idx = tid + i * 256;          // 0..2047
      int r = idx >> 4, u = idx & 15;   // 16 float4 per row
      int grow = bm + r;
      float4 v = make_float4(0.f, 0.f, 0.f, 0.f);
      if (grow < M) v = *(const float4*)(A + (size_t)grow * K + k0 + u * 4);
      __nv_bfloat16 h0 = __float2bfloat16_rn(v.x), h1 = __float2bfloat16_rn(v.y);
      __nv_bfloat16 h2 = __float2bfloat16_rn(v.z), h3 = __float2bfloat16_rn(v.w);
      __nv_bfloat16 l0 = __float2bfloat16_rn(v.x - __bfloat162float(h0));
      __nv_bfloat16 l1 = __float2bfloat16_rn(v.y - __bfloat162float(h1));
      __nv_bfloat16 l2 = __float2bfloat16_rn(v.z - __bfloat162float(h2));
      __nv_bfloat16 l3 = __float2bfloat16_rn(v.w - __bfloat162float(h3));
      union { __nv_bfloat162 b[2]; uint2 u2; } H, L;
      H.b[0] = __halves2bfloat162(h0, h1); H.b[1] = __halves2bfloat162(h2, h3);
      L.b[0] = __halves2bfloat162(l0, l1); L.b[1] = __halves2bfloat162(l2, l3);
      *(uint2*)(sAh + r * SROW + u * 4) = H.u2;
      *(uint2*)(sAl + r * SROW + u * 4) = L.u2;
    }
    // ---- B chunk: 128 rows x 64 bf16 (pre-split) ----
#pragma unroll
    for (int i = 0; i < 4; ++i) {
      int idx = tid + i * 256;          // 0..1023
      int r = idx >> 3, u = idx & 7;    // 8 uint4 per row
      uint4 vh = *(const uint4*)(Bhi + (size_t)(bn + r) * K + k0 + u * 8);
      uint4 vl = *(const uint4*)(Blo + (size_t)(bn + r) * K + k0 + u * 8);
      *(uint4*)(sBh + r * SROW + u * 8) = vh;
      *(uint4*)(sBl + r * SROW + u * 8) = vl;
    }
    __syncthreads();

    // ---- compute: 4 k16 steps ----
#pragma unroll
    for (int ks = 0; ks < 4; ++ks) {
      int kk = ks * 16 + lc * 2;
      uint32_t ah[4][4], al[4][4], bh[4][2], bl[4][2];
#pragma unroll
      for (int mt = 0; mt < 4; ++mt) {
        const __nv_bfloat16* p0 = sAh + (wm + mt * 16 + lr) * SROW + kk;
        const __nv_bfloat16* p1 = sAl + (wm + mt * 16 + lr) * SROW + kk;
        ah[mt][0] = *(const uint32_t*)p0;
        ah[mt][1] = *(const uint32_t*)(p0 + 8 * SROW);
        ah[mt][2] = *(const uint32_t*)(p0 + 8);
        ah[mt][3] = *(const uint32_t*)(p0 + 8 * SROW + 8);
        al[mt][0] = *(const uint32_t*)p1;
        al[mt][1] = *(const uint32_t*)(p1 + 8 * SROW);
        al[mt][2] = *(const uint32_t*)(p1 + 8);
        al[mt][3] = *(const uint32_t*)(p1 + 8 * SROW + 8);
      }
#pragma unroll
      for (int nt = 0; nt < 4; ++nt) {
        const __nv_bfloat16* q0 = sBh + (wn + nt * 8 + lr) * SROW + kk;
        const __nv_bfloat16* q1 = sBl + (wn + nt * 8 + lr) * SROW + kk;
        bh[nt][0] = *(const uint32_t*)q0;
        bh[nt][1] = *(const uint32_t*)(q0 + 8);
        bl[nt][0] = *(const uint32_t*)q1;
        bl[nt][1] = *(const uint32_t*)(q1 + 8);
      }
#pragma unroll
      for (int mt = 0; mt < 4; ++mt)
#pragma unroll
        for (int nt = 0; nt < 4; ++nt) {
          mma16816(acc[mt][nt], ah[mt], bh[nt]);
          mma16816(acc[mt][nt], ah[mt], bl[nt]);
          mma16816(acc[mt][nt], al[mt], bh[nt]);
        }
    }
    __syncthreads();
  }

  // ---- epilogue ----
#pragma unroll
  for (int mt = 0; mt < 4; ++mt) {
    int row0 = bm + wm + mt * 16 + lr;
#pragma unroll
    for (int nt = 0; nt < 4; ++nt) {
      int col = bn + wn + nt * 8 + lc * 2;
      if (row0 < M)
        *(float2*)(C + (size_t)row0 * N + col) =
            make_float2(acc[mt][nt][0], acc[mt][nt][1]);
      if (row0 + 8 < M)
        *(float2*)(C + (size_t)(row0 + 8) * N + col) =
            make_float2(acc[mt][nt][2], acc[mt][nt][3]);
    }
  }
}

// ---------------- layer 1 (2 heads of 128) ----------------

__global__ void alpha1_kernel(int Nn, const float* __restrict__ a_s,
                              const float* __restrict__ a_d) {
  int gw = (blockIdx.x * blockDim.x + threadIdx.x) >> 5;
  int lane = threadIdx.x & 31;
  int n = gw >> 1, head = gw & 1;
  if (n >= Nn) return;
  const float* hp = g_h1 + (size_t)n * 256 + head * 128;
  const float* asp = a_s + head * 128;
  const float* adp = a_d + head * 128;
  float s = 0.f, d = 0.f;
#pragma unroll
  for (int c = lane; c < 128; c += 32) {
    float hv = hp[c];
    s = fmaf(hv, asp[c], s);
    d = fmaf(hv, adp[c], d);
  }
#pragma unroll
  for (int o = 16; o; o >>= 1) {
    s += __shfl_xor_sync(0xffffffffu, s, o);
    d += __shfl_xor_sync(0xffffffffu, d, o);
  }
  if (lane == 0) {
    ((float*)g_as1)[n * 2 + head] = s;
    ((float*)g_ad1)[n * 2 + head] = d;
    ((float*)g_m1)[n * 2 + head] = leaky(s + d);
  }
}

__global__ void edge_max1_kernel(const int* __restrict__ ei, int E) {
  int e = blockIdx.x * blockDim.x + threadIdx.x;
  if (e >= E) return;
  int s = __ldg(ei + e), d = __ldg(ei + E + e);
  float2 a = g_as1[s], b = g_ad1[d];
  atomicMaxF(&((float*)g_m1)[2 * d], leaky(a.x + b.x));
  atomicMaxF(&((float*)g_m1)[2 * d + 1], leaky(a.y + b.y));
}

__global__ void init1_kernel(int Nn) {
  int idx = blockIdx.x * blockDim.x + threadIdx.x;
  if (idx >= Nn * 64) return;
  int n = idx >> 6, c4 = idx & 63;
  float2 a = g_as1[n], b = g_ad1[n], mm = g_m1[n];
  float ex0 = __expf(leaky(a.x + b.x) - mm.x);
  float ex1 = __expf(leaky(a.y + b.y) - mm.y);
  if (c4 == 0) g_den1[n] = make_float2(ex0, ex1);
  float ex = (c4 >= 32) ? ex1 : ex0;
  float4 v = *((const float4*)g_h1 + (size_t)n * 64 + c4);
  v.x *= ex; v.y *= ex; v.z *= ex; v.w *= ex;
  *((float4*)g_acc1 + (size_t)n * 64 + c4) = v;
}

__global__ void edge_acc1_kernel(const int* __restrict__ ei, int E) {
  int gw = (blockIdx.x * blockDim.x + threadIdx.x) >> 5;
  int lane = threadIdx.x & 31;
  if (gw >= E) return;
  int s = __ldg(ei + gw), d = __ldg(ei + E + gw);
  float2 a = g_as1[s], b = g_ad1[d], mm = g_m1[d];
  float ex0 = __expf(leaky(a.x + b.x) - mm.x);
  float ex1 = __expf(leaky(a.y + b.y) - mm.y);
  if (lane == 0) atomicAdd(&((float*)g_den1)[2 * d], ex0);
  if (lane == 1) atomicAdd(&((float*)g_den1)[2 * d + 1], ex1);
  const float4* hs = (const float4*)g_h1 + (size_t)s * 64;
  float* ac = g_acc1 + (size_t)d * 256;
#pragma unroll
  for (int i = 0; i < 2; ++i) {
    int c4 = i * 32 + lane;
    float ex = (c4 >= 32) ? ex1 : ex0;
    float4 v = __ldg(hs + c4);
    v.x *= ex; v.y *= ex; v.z *= ex; v.w *= ex;
    red_add_v4(ac + c4 * 4, v);
  }
}

__global__ void fin1_kernel(int Nn, const float* __restrict__ b1) {
  int idx = blockIdx.x * blockDim.x + threadIdx.x;
  if (idx >= Nn * 64) return;
  int n = idx >> 6, c4 = idx & 63;
  float2 dd = g_den1[n];
  float ds = (c4 >= 32) ? dd.y : dd.x;
  float inv = 1.0f / ds;
  float4 v = *((float4*)g_acc1 + idx);
  float4 bb = __ldg((const float4*)b1 + c4);
  v.x = v.x * inv + bb.x; v.y = v.y * inv + bb.y;
  v.z = v.z * inv + bb.z; v.w = v.w * inv + bb.w;
  v.x = v.x > 0.f ? v.x : expm1f(v.x);
  v.y = v.y > 0.f ? v.y : expm1f(v.y);
  v.z = v.z > 0.f ? v.z : expm1f(v.z);
  v.w = v.w > 0.f ? v.w : expm1f(v.w);
  *((float4*)g_acc1 + idx) = v;
}

// ---------------- layer 2 (1 head of 128) ----------------

__global__ void alpha2_kernel(int Nn, const float* __restrict__ a_s,
                              const float* __restrict__ a_d) {
  int n = (blockIdx.x * blockDim.x + threadIdx.x) >> 5;
  int lane = threadIdx.x & 31;
  if (n >= Nn) return;
  const float* hp = g_h2 + (size_t)n * 128;
  float s = 0.f, d = 0.f;
#pragma unroll
  for (int c = lane; c < 128; c += 32) {
    float hv = hp[c];
    s = fmaf(hv, a_s[c], s);
    d = fmaf(hv, a_d[c], d);
  }
#pragma unroll
  for (int o = 16; o; o >>= 1) {
    s += __shfl_xor_sync(0xffffffffu, s, o);
    d += __shfl_xor_sync(0xffffffffu, d, o);
  }
  if (lane == 0) {
    g_as2[n] = s;
    g_ad2[n] = d;
    g_m2[n] = leaky(s + d);
  }
}

__global__ void edge_max2_kernel(const int* __restrict__ ei, int E) {
  int e = blockIdx.x * blockDim.x + threadIdx.x;
  if (e >= E) return;
  int s = __ldg(ei + e), d = __ldg(ei + E + e);
  atomicMaxF(&g_m2[d], leaky(g_as2[s] + g_ad2[d]));
}

__global__ void init2_kernel(int Nn, float* __restrict__ out) {
  int idx = blockIdx.x * blockDim.x + threadIdx.x;
  if (idx >= Nn * 32) return;
  int n = idx >> 5, c4 = idx & 31;
  float ex = __expf(leaky(g_as2[n] + g_ad2[n]) - g_m2[n]);
  if (c4 == 0) g_den2[n] = ex;
  float4 v = *((const float4*)g_h2 + (size_t)n * 32 + c4);
  v.x *= ex; v.y *= ex; v.z *= ex; v.w *= ex;
  *((float4*)out + idx) = v;
}

__global__ void edge_acc2_kernel(const int* __restrict__ ei, int E,
                                 float* __restrict__ out) {
  int gw = (blockIdx.x * blockDim.x + threadIdx.x) >> 5;
  int lane = threadIdx.x & 31;
  if (gw >= E) return;
  int s = __ldg(ei + gw), d = __ldg(ei + E + gw);
  float ex = __expf(leaky(g_as2[s] + g_ad2[d]) - g_m2[d]);
  if (lane == 0) atomicAdd(&g_den2[d], ex);
  float4 v = __ldg((const float4*)g_h2 + (size_t)s * 32 + lane);
  v.x *= ex; v.y *= ex; v.z *= ex; v.w *= ex;
  red_add_v4(out + (size_t)d * 128 + lane * 4, v);
}

__global__ void fin2_kernel(int Nn, const float* __restrict__ b2,
                            float* __restrict__ out) {
  int idx = blockIdx.x * blockDim.x + threadIdx.x;
  if (idx >= Nn * 32) return;
  int n = idx >> 5, c4 = idx & 31;
  float inv = 1.0f / g_den2[n];
  float4 v = *((float4*)out + idx);
  float4 bb = __ldg((const float4*)b2 + c4);
  v.x = v.x * inv + bb.x; v.y = v.y * inv + bb.y;
  v.z = v.z * inv + bb.z; v.w = v.w * inv + bb.w;
  *((float4*)out + idx) = v;
}

// ---------------- host launcher ----------------
extern "C" void kernel_launch(void* const* d_in, const int* in_sizes, int n_in,
                              void* d_out, int out_size) {
  const float* x     = (const float*)d_in[0];
  const int*   ei    = (const int*)d_in[1];
  const float* W1    = (const float*)d_in[2];
  const float* a_s1  = (const float*)d_in[3];
  const float* a_d1  = (const float*)d_in[4];
  const float* b1    = (const float*)d_in[5];
  const float* W2    = (const float*)d_in[6];
  const float* a_s2  = (const float*)d_in[7];
  const float* a_d2  = (const float*)d_in[8];
  const float* b2    = (const float*)d_in[9];
  float* out = (float*)d_out;

  int Nn = in_sizes[0] / 256;
  int E  = in_sizes[1] / 2;
  int MT = (Nn + 127) / 128;

  float *p_h1, *p_acc1, *p_h2;
  __nv_bfloat16 *p_w1h, *p_w1l, *p_w2h, *p_w2l;
  cudaGetSymbolAddress((void**)&p_h1, g_h1);
  cudaGetSymbolAddress((void**)&p_acc1, g_acc1);
  cudaGetSymbolAddress((void**)&p_h2, g_h2);
  cudaGetSymbolAddress((void**)&p_w1h, g_w1t_hi);
  cudaGetSymbolAddress((void**)&p_w1l, g_w1t_lo);
  cudaGetSymbolAddress((void**)&p_w2h, g_w2t_hi);
  cudaGetSymbolAddress((void**)&p_w2l, g_w2t_lo);

  constexpr uint32_t GSMEM = 4u * 128u * SROW * 2u;  // 73728 B
  cudaFuncSetAttribute(gemm_mma_kernel,
                       cudaFuncAttributeMaxDynamicSharedMemorySize, GSMEM);

  const int TB = 256;

  // weight prep (independent of x)
  wprep_kernel<<<(256 * 256 + TB - 1) / TB, TB>>>(W1, 256, 256, p_w1h, p_w1l);
  wprep_kernel<<<(256 * 128 + TB - 1) / TB, TB>>>(W2, 256, 128, p_w2h, p_w2l);

  // ---- layer 1 ----
  {
    dim3 grid(2, MT);  // N=256 -> 2 column blocks
    gemm_mma_kernel<<<grid, TB, GSMEM>>>(x, p_w1h, p_w1l, p_h1, Nn, 256);
  }
  alpha1_kernel<<<(Nn * 2 * 32 + TB - 1) / TB, TB>>>(Nn, a_s1, a_d1);
  edge_max1_kernel<<<(E + TB - 1) / TB, TB>>>(ei, E);
  init1_kernel<<<(Nn * 64 + TB - 1) / TB, TB>>>(Nn);
  edge_acc1_kernel<<<(E * 32 + TB - 1) / TB, TB>>>(ei, E);
  fin1_kernel<<<(Nn * 64 + TB - 1) / TB, TB>>>(Nn, b1);

  // ---- layer 2 ----
  {
    dim3 grid(1, MT);  // N=128 -> 1 column block
    gemm_mma_kernel<<<grid, TB, GSMEM>>>(p_acc1, p_w2h, p_w2l, p_h2, Nn, 128);
  }
  alpha2_kernel<<<(Nn * 32 + TB - 1) / TB, TB>>>(Nn, a_s2, a_d2);
  edge_max2_kernel<<<(E + TB - 1) / TB, TB>>>(ei, E);
  init2_kernel<<<(Nn * 32 + TB - 1) / TB, TB>>>(Nn, out);
  edge_acc2_kernel<<<(E * 32 + TB - 1) / TB, TB>>>(ei, E, out);
  fin2_kernel<<<(Nn * 32 + TB - 1) / TB, TB>>>(Nn, b2, out);
}

// round 5
// speedup vs baseline: 2.3070x; 1.7047x over previous
#include <cuda_runtime.h>
#include <cuda_bf16.h>
#include <cstdint>
#include <cstddef>

// Problem constants (fixed by the dataset)
#define NN 50000
#define EE 800000

// ---------------- device scratch (no allocs allowed) ----------------
__device__ float  g_h1[NN * 256];    // x @ W1
__device__ float  g_acc1[NN * 256];  // layer-1 output (ELU'd hidden)
__device__ float  g_h2[NN * 128];    // hidden @ W2
__device__ float2 g_as1[NN], g_ad1[NN];
__device__ float  g_as2[NN], g_ad2[NN];
// transposed + bf16-split weights: [N][K] K-major
__device__ __nv_bfloat16 g_w1t_hi[256 * 256], g_w1t_lo[256 * 256];
__device__ __nv_bfloat16 g_w2t_hi[128 * 256], g_w2t_lo[128 * 256];
// CSR (built once per call, shared by both layers)
__device__ int g_deg[NN], g_cur[NN], g_rowp[NN + 1], g_bsum[64];
__device__ int g_csr[EE];

// ---------------- misc helpers ----------------
__device__ __forceinline__ float leaky(float x) { return x > 0.f ? x : 0.2f * x; }

__device__ __forceinline__ void mma16816(float* c, const uint32_t* a,
                                         const uint32_t* b) {
  asm volatile(
      "mma.sync.aligned.m16n8k16.row.col.f32.bf16.bf16.f32 "
      "{%0,%1,%2,%3}, {%4,%5,%6,%7}, {%8,%9}, {%0,%1,%2,%3};"
      : "+f"(c[0]), "+f"(c[1]), "+f"(c[2]), "+f"(c[3])
      : "r"(a[0]), "r"(a[1]), "r"(a[2]), "r"(a[3]), "r"(b[0]), "r"(b[1]));
}

// ---------------- CSR build ----------------
__global__ void zero_deg_kernel(int Nn) {
  int i = blockIdx.x * blockDim.x + threadIdx.x;
  if (i < Nn) g_deg[i] = 0;
}

__global__ void hist_kernel(const int* __restrict__ ei, int E) {
  int e = blockIdx.x * blockDim.x + threadIdx.x;
  if (e < E) atomicAdd(&g_deg[__ldg(ei + E + e)], 1);
}

__global__ void scan1_kernel(int Nn) {  // per-1024-chunk exclusive scan
  __shared__ int sm[1024];
  int tid = threadIdx.x;
  int i = blockIdx.x * 1024 + tid;
  int v = (i < Nn) ? g_deg[i] : 0;
  sm[tid] = v;
  __syncthreads();
#pragma unroll
  for (int off = 1; off < 1024; off <<= 1) {
    int t = (tid >= off) ? sm[tid - off] : 0;
    __syncthreads();
    sm[tid] += t;
    __syncthreads();
  }
  if (i < Nn) g_rowp[i] = sm[tid] - v;  // local exclusive
  if (tid == 1023) g_bsum[blockIdx.x] = sm[1023];
}

__global__ void scan2_kernel(int nb) {  // exclusive scan of block sums (nb<=64)
  __shared__ int sm[64];
  int tid = threadIdx.x;
  int v = (tid < nb) ? g_bsum[tid] : 0;
  sm[tid] = v;
  __syncthreads();
#pragma unroll
  for (int off = 1; off < 64; off <<= 1) {
    int t = (tid >= off) ? sm[tid - off] : 0;
    __syncthreads();
    sm[tid] += t;
    __syncthreads();
  }
  if (tid < nb) g_bsum[tid] = sm[tid] - v;
}

__global__ void scan3_kernel(int Nn, int E) {
  int i = blockIdx.x * blockDim.x + threadIdx.x;
  if (i < Nn) {
    int r = g_rowp[i] + g_bsum[i >> 10];
    g_rowp[i] = r;
    g_cur[i] = r;
  }
  if (i == 0) g_rowp[Nn] = E;
}

__global__ void scatter_kernel(const int* __restrict__ ei, int E) {
  int e = blockIdx.x * blockDim.x + threadIdx.x;
  if (e >= E) return;
  int s = __ldg(ei + e), d = __ldg(ei + E + e);
  int p = atomicAdd(&g_cur[d], 1);
  g_csr[p] = s;
}

// ---------------- weight prep: W[K,N] fp32 -> Wt hi/lo bf16 [N,K] ----------------
__global__ void wprep_kernel(const float* __restrict__ W, int K, int N,
                             __nv_bfloat16* __restrict__ hi,
                             __nv_bfloat16* __restrict__ lo) {
  int idx = blockIdx.x * blockDim.x + threadIdx.x;
  if (idx >= K * N) return;
  int k = idx / N, n = idx % N;
  float v = W[idx];
  __nv_bfloat16 h = __float2bfloat16_rn(v);
  hi[n * K + k] = h;
  lo[n * K + k] = __float2bfloat16_rn(v - __bfloat162float(h));
}

// ---------------- mma.sync GEMM: C[M,N] = A[M,256] @ Bt^T (BF16x3 split) ----------------
#define SROW 72
__global__ __launch_bounds__(256) void gemm_mma_kernel(
    const float* __restrict__ A, const __nv_bfloat16* __restrict__ Bhi,
    const __nv_bfloat16* __restrict__ Blo, float* __restrict__ C, int M, int N) {
  constexpr int K = 256;
  extern __shared__ __nv_bfloat16 sm[];
  __nv_bfloat16* sAh = sm;
  __nv_bfloat16* sAl = sm + 128 * SROW;
  __nv_bfloat16* sBh = sm + 2 * 128 * SROW;
  __nv_bfloat16* sBl = sm + 3 * 128 * SROW;

  int tid = threadIdx.x, wid = tid >> 5, lane = tid & 31;
  int bm = blockIdx.y * 128, bn = blockIdx.x * 128;
  int wm = (wid >> 2) * 64, wn = (wid & 3) * 32;
  int lr = lane >> 2, lc = lane & 3;

  float acc[4][4][4];
#pragma unroll
  for (int i = 0; i < 4; i++)
#pragma unroll
    for (int j = 0; j < 4; j++)
#pragma unroll
      for (int q = 0; q < 4; q++) acc[i][j][q] = 0.f;

  for (int c = 0; c < 4; ++c) {
    int k0 = c * 64;
#pragma unroll
    for (int i = 0; i < 8; ++i) {
      int idx = tid + i * 256;
      int r = idx >> 4, u = idx & 15;
      int grow = bm + r;
      float4 v = make_float4(0.f, 0.f, 0.f, 0.f);
      if (grow < M) v = *(const float4*)(A + (size_t)grow * K + k0 + u * 4);
      __nv_bfloat16 h0 = __float2bfloat16_rn(v.x), h1 = __float2bfloat16_rn(v.y);
      __nv_bfloat16 h2 = __float2bfloat16_rn(v.z), h3 = __float2bfloat16_rn(v.w);
      __nv_bfloat16 l0 = __float2bfloat16_rn(v.x - __bfloat162float(h0));
      __nv_bfloat16 l1 = __float2bfloat16_rn(v.y - __bfloat162float(h1));
      __nv_bfloat16 l2 = __float2bfloat16_rn(v.z - __bfloat162float(h2));
      __nv_bfloat16 l3 = __float2bfloat16_rn(v.w - __bfloat162float(h3));
      union { __nv_bfloat162 b[2]; uint2 u2; } H, L;
      H.b[0] = __halves2bfloat162(h0, h1); H.b[1] = __halves2bfloat162(h2, h3);
      L.b[0] = __halves2bfloat162(l0, l1); L.b[1] = __halves2bfloat162(l2, l3);
      *(uint2*)(sAh + r * SROW + u * 4) = H.u2;
      *(uint2*)(sAl + r * SROW + u * 4) = L.u2;
    }
#pragma unroll
    for (int i = 0; i < 4; ++i) {
      int idx = tid + i * 256;
      int r = idx >> 3, u = idx & 7;
      uint4 vh = *(const uint4*)(Bhi + (size_t)(bn + r) * K + k0 + u * 8);
      uint4 vl = *(const uint4*)(Blo + (size_t)(bn + r) * K + k0 + u * 8);
      *(uint4*)(sBh + r * SROW + u * 8) = vh;
      *(uint4*)(sBl + r * SROW + u * 8) = vl;
    }
    __syncthreads();

#pragma unroll
    for (int ks = 0; ks < 4; ++ks) {
      int kk = ks * 16 + lc * 2;
      uint32_t ah[4][4], al[4][4], bh[4][2], bl[4][2];
#pragma unroll
      for (int mt = 0; mt < 4; ++mt) {
        const __nv_bfloat16* p0 = sAh + (wm + mt * 16 + lr) * SROW + kk;
        const __nv_bfloat16* p1 = sAl + (wm + mt * 16 + lr) * SROW + kk;
        ah[mt][0] = *(const uint32_t*)p0;
        ah[mt][1] = *(const uint32_t*)(p0 + 8 * SROW);
        ah[mt][2] = *(const uint32_t*)(p0 + 8);
        ah[mt][3] = *(const uint32_t*)(p0 + 8 * SROW + 8);
        al[mt][0] = *(const uint32_t*)p1;
        al[mt][1] = *(const uint32_t*)(p1 + 8 * SROW);
        al[mt][2] = *(const uint32_t*)(p1 + 8);
        al[mt][3] = *(const uint32_t*)(p1 + 8 * SROW + 8);
      }
#pragma unroll
      for (int nt = 0; nt < 4; ++nt) {
        const __nv_bfloat16* q0 = sBh + (wn + nt * 8 + lr) * SROW + kk;
        const __nv_bfloat16* q1 = sBl + (wn + nt * 8 + lr) * SROW + kk;
        bh[nt][0] = *(const uint32_t*)q0;
        bh[nt][1] = *(const uint32_t*)(q0 + 8);
        bl[nt][0] = *(const uint32_t*)q1;
        bl[nt][1] = *(const uint32_t*)(q1 + 8);
      }
#pragma unroll
      for (int mt = 0; mt < 4; ++mt)
#pragma unroll
        for (int nt = 0; nt < 4; ++nt) {
          mma16816(acc[mt][nt], ah[mt], bh[nt]);
          mma16816(acc[mt][nt], ah[mt], bl[nt]);
          mma16816(acc[mt][nt], al[mt], bh[nt]);
        }
    }
    __syncthreads();
  }

#pragma unroll
  for (int mt = 0; mt < 4; ++mt) {
    int row0 = bm + wm + mt * 16 + lr;
#pragma unroll
    for (int nt = 0; nt < 4; ++nt) {
      int col = bn + wn + nt * 8 + lc * 2;
      if (row0 < M)
        *(float2*)(C + (size_t)row0 * N + col) =
            make_float2(acc[mt][nt][0], acc[mt][nt][1]);
      if (row0 + 8 < M)
        *(float2*)(C + (size_t)(row0 + 8) * N + col) =
            make_float2(acc[mt][nt][2], acc[mt][nt][3]);
    }
  }
}

// ---------------- attention dots ----------------
__global__ void alpha1_kernel(int Nn, const float* __restrict__ a_s,
                              const float* __restrict__ a_d) {
  int gw = (blockIdx.x * blockDim.x + threadIdx.x) >> 5;
  int lane = threadIdx.x & 31;
  int n = gw >> 1, head = gw & 1;
  if (n >= Nn) return;
  const float* hp = g_h1 + (size_t)n * 256 + head * 128;
  const float* asp = a_s + head * 128;
  const float* adp = a_d + head * 128;
  float s = 0.f, d = 0.f;
#pragma unroll
  for (int c = lane; c < 128; c += 32) {
    float hv = hp[c];
    s = fmaf(hv, asp[c], s);
    d = fmaf(hv, adp[c], d);
  }
#pragma unroll
  for (int o = 16; o; o >>= 1) {
    s += __shfl_xor_sync(0xffffffffu, s, o);
    d += __shfl_xor_sync(0xffffffffu, d, o);
  }
  if (lane == 0) {
    ((float*)g_as1)[n * 2 + head] = s;
    ((float*)g_ad1)[n * 2 + head] = d;
  }
}

__global__ void alpha2_kernel(int Nn, const float* __restrict__ a_s,
                              const float* __restrict__ a_d) {
  int n = (blockIdx.x * blockDim.x + threadIdx.x) >> 5;
  int lane = threadIdx.x & 31;
  if (n >= Nn) return;
  const float* hp = g_h2 + (size_t)n * 128;
  float s = 0.f, d = 0.f;
#pragma unroll
  for (int c = lane; c < 128; c += 32) {
    float hv = hp[c];
    s = fmaf(hv, a_s[c], s);
    d = fmaf(hv, a_d[c], d);
  }
#pragma unroll
  for (int o = 16; o; o >>= 1) {
    s += __shfl_xor_sync(0xffffffffu, s, o);
    d += __shfl_xor_sync(0xffffffffu, d, o);
  }
  if (lane == 0) {
    g_as2[n] = s;
    g_ad2[n] = d;
  }
}

// ---------------- fused softmax + aggregate, warp per dst node ----------------
// layer 1: 2 heads x 128 ch. lane owns float4 c4=lane (head0) and c4=lane+32 (head1).
__global__ __launch_bounds__(256) void agg1_kernel(int Nn,
                                                   const float* __restrict__ b1) {
  int w = (blockIdx.x * blockDim.x + threadIdx.x) >> 5;
  int lane = threadIdx.x & 31;
  if (w >= Nn) return;
  int beg = g_rowp[w], end = g_rowp[w + 1];
  float2 ad = g_ad1[w], as = g_as1[w];
  float s0 = leaky(as.x + ad.x), s1 = leaky(as.y + ad.y);
  float m0 = s0, m1 = s1;
  for (int i = beg + lane; i < end; i += 32) {
    float2 a = g_as1[g_csr[i]];
    m0 = fmaxf(m0, leaky(a.x + ad.x));
    m1 = fmaxf(m1, leaky(a.y + ad.y));
  }
#pragma unroll
  for (int o = 16; o; o >>= 1) {
    m0 = fmaxf(m0, __shfl_xor_sync(0xffffffffu, m0, o));
    m1 = fmaxf(m1, __shfl_xor_sync(0xffffffffu, m1, o));
  }
  float den0 = __expf(s0 - m0), den1 = __expf(s1 - m1);
  const float4* hv = (const float4*)g_h1;
  float4 acc0 = __ldg(hv + (size_t)w * 64 + lane);
  float4 acc1 = __ldg(hv + (size_t)w * 64 + 32 + lane);
  acc0.x *= den0; acc0.y *= den0; acc0.z *= den0; acc0.w *= den0;
  acc1.x *= den1; acc1.y *= den1; acc1.z *= den1; acc1.w *= den1;

  for (int base = beg; base < end; base += 32) {
    int i = base + lane;
    int src = 0;
    float ex0 = 0.f, ex1 = 0.f;
    if (i < end) {
      src = g_csr[i];
      float2 a = g_as1[src];
      ex0 = __expf(leaky(a.x + ad.x) - m0);
      ex1 = __expf(leaky(a.y + ad.y) - m1);
    }
    int cnt = min(32, end - base);
    for (int j = 0; j < cnt; ++j) {
      int sj = __shfl_sync(0xffffffffu, src, j);
      float e0 = __shfl_sync(0xffffffffu, ex0, j);
      float e1 = __shfl_sync(0xffffffffu, ex1, j);
      const float4* hs = hv + (size_t)sj * 64;
      float4 v0 = __ldg(hs + lane);
      float4 v1 = __ldg(hs + 32 + lane);
      acc0.x = fmaf(v0.x, e0, acc0.x); acc0.y = fmaf(v0.y, e0, acc0.y);
      acc0.z = fmaf(v0.z, e0, acc0.z); acc0.w = fmaf(v0.w, e0, acc0.w);
      acc1.x = fmaf(v1.x, e1, acc1.x); acc1.y = fmaf(v1.y, e1, acc1.y);
      acc1.z = fmaf(v1.z, e1, acc1.z); acc1.w = fmaf(v1.w, e1, acc1.w);
      den0 += e0;
      den1 += e1;
    }
  }
  float i0 = 1.f / den0, i1 = 1.f / den1;
  float4 bb0 = __ldg((const float4*)b1 + lane);
  float4 bb1 = __ldg((const float4*)b1 + 32 + lane);
  float4 o0, o1;
  o0.x = acc0.x * i0 + bb0.x; o0.y = acc0.y * i0 + bb0.y;
  o0.z = acc0.z * i0 + bb0.z; o0.w = acc0.w * i0 + bb0.w;
  o1.x = acc1.x * i1 + bb1.x; o1.y = acc1.y * i1 + bb1.y;
  o1.z = acc1.z * i1 + bb1.z; o1.w = acc1.w * i1 + bb1.w;
  o0.x = o0.x > 0.f ? o0.x : expm1f(o0.x);
  o0.y = o0.y > 0.f ? o0.y : expm1f(o0.y);
  o0.z = o0.z > 0.f ? o0.z : expm1f(o0.z);
  o0.w = o0.w > 0.f ? o0.w : expm1f(o0.w);
  o1.x = o1.x > 0.f ? o1.x : expm1f(o1.x);
  o1.y = o1.y > 0.f ? o1.y : expm1f(o1.y);
  o1.z = o1.z > 0.f ? o1.z : expm1f(o1.z);
  o1.w = o1.w > 0.f ? o1.w : expm1f(o1.w);
  ((float4*)g_acc1)[(size_t)w * 64 + lane] = o0;
  ((float4*)g_acc1)[(size_t)w * 64 + 32 + lane] = o1;
}

// layer 2: 1 head x 128 ch. lane owns float4 c4=lane.
__global__ __launch_bounds__(256) void agg2_kernel(int Nn,
                                                   const float* __restrict__ b2,
                                                   float* __restrict__ out) {
  int w = (blockIdx.x * blockDim.x + threadIdx.x) >> 5;
  int lane = threadIdx.x & 31;
  if (w >= Nn) return;
  int beg = g_rowp[w], end = g_rowp[w + 1];
  float ad = g_ad2[w], as = g_as2[w];
  float s = leaky(as + ad);
  float m = s;
  for (int i = beg + lane; i < end; i += 32)
    m = fmaxf(m, leaky(g_as2[g_csr[i]] + ad));
#pragma unroll
  for (int o = 16; o; o >>= 1) m = fmaxf(m, __shfl_xor_sync(0xffffffffu, m, o));
  float den = __expf(s - m);
  const float4* hv = (const float4*)g_h2;
  float4 acc = __ldg(hv + (size_t)w * 32 + lane);
  acc.x *= den; acc.y *= den; acc.z *= den; acc.w *= den;

  for (int base = beg; base < end; base += 32) {
    int i = base + lane;
    int src = 0;
    float ex = 0.f;
    if (i < end) {
      src = g_csr[i];
      ex = __expf(leaky(g_as2[src] + ad) - m);
    }
    int cnt = min(32, end - base);
    for (int j = 0; j < cnt; ++j) {
      int sj = __shfl_sync(0xffffffffu, src, j);
      float e = __shfl_sync(0xffffffffu, ex, j);
      float4 v = __ldg(hv + (size_t)sj * 32 + lane);
      acc.x = fmaf(v.x, e, acc.x); acc.y = fmaf(v.y, e, acc.y);
      acc.z = fmaf(v.z, e, acc.z); acc.w = fmaf(v.w, e, acc.w);
      den += e;
    }
  }
  float inv = 1.f / den;
  float4 bb = __ldg((const float4*)b2 + lane);
  float4 o;
  o.x = acc.x * inv + bb.x; o.y = acc.y * inv + bb.y;
  o.z = acc.z * inv + bb.z; o.w = acc.w * inv + bb.w;
  ((float4*)out)[(size_t)w * 32 + lane] = o;
}

// ---------------- host launcher ----------------
extern "C" void kernel_launch(void* const* d_in, const int* in_sizes, int n_in,
                              void* d_out, int out_size) {
  const float* x     = (const float*)d_in[0];
  const int*   ei    = (const int*)d_in[1];
  const float* W1    = (const float*)d_in[2];
  const float* a_s1  = (const float*)d_in[3];
  const float* a_d1  = (const float*)d_in[4];
  const float* b1    = (const float*)d_in[5];
  const float* W2    = (const float*)d_in[6];
  const float* a_s2  = (const float*)d_in[7];
  const float* a_d2  = (const float*)d_in[8];
  const float* b2    = (const float*)d_in[9];
  float* out = (float*)d_out;

  int Nn = in_sizes[0] / 256;
  int E  = in_sizes[1] / 2;
  int MT = (Nn + 127) / 128;
  int nb = (Nn + 1023) / 1024;

  float *p_h1, *p_acc1, *p_h2;
  __nv_bfloat16 *p_w1h, *p_w1l, *p_w2h, *p_w2l;
  cudaGetSymbolAddress((void**)&p_h1, g_h1);
  cudaGetSymbolAddress((void**)&p_acc1, g_acc1);
  cudaGetSymbolAddress((void**)&p_h2, g_h2);
  cudaGetSymbolAddress((void**)&p_w1h, g_w1t_hi);
  cudaGetSymbolAddress((void**)&p_w1l, g_w1t_lo);
  cudaGetSymbolAddress((void**)&p_w2h, g_w2t_hi);
  cudaGetSymbolAddress((void**)&p_w2l, g_w2t_lo);

  constexpr uint32_t GSMEM = 4u * 128u * SROW * 2u;  // 73728 B
  cudaFuncSetAttribute(gemm_mma_kernel,
                       cudaFuncAttributeMaxDynamicSharedMemorySize, GSMEM);

  const int TB = 256;

  // ---- CSR build (edge structure; independent of features) ----
  zero_deg_kernel<<<(Nn + TB - 1) / TB, TB>>>(Nn);
  hist_kernel<<<(E + TB - 1) / TB, TB>>>(ei, E);
  scan1_kernel<<<nb, 1024>>>(Nn);
  scan2_kernel<<<1, 64>>>(nb);
  scan3_kernel<<<(Nn + TB - 1) / TB, TB>>>(Nn, E);
  scatter_kernel<<<(E + TB - 1) / TB, TB>>>(ei, E);

  // ---- weight prep ----
  wprep_kernel<<<(256 * 256 + TB - 1) / TB, TB>>>(W1, 256, 256, p_w1h, p_w1l);
  wprep_kernel<<<(256 * 128 + TB - 1) / TB, TB>>>(W2, 256, 128, p_w2h, p_w2l);

  // ---- layer 1 ----
  {
    dim3 grid(2, MT);
    gemm_mma_kernel<<<grid, TB, GSMEM>>>(x, p_w1h, p_w1l, p_h1, Nn, 256);
  }
  alpha1_kernel<<<(Nn * 2 * 32 + TB - 1) / TB, TB>>>(Nn, a_s1, a_d1);
  agg1_kernel<<<(Nn * 32 + TB - 1) / TB, TB>>>(Nn, b1);

  // ---- layer 2 ----
  {
    dim3 grid(1, MT);
    gemm_mma_kernel<<<grid, TB, GSMEM>>>(p_acc1, p_w2h, p_w2l, p_h2, Nn, 128);
  }
  alpha2_kernel<<<(Nn * 32 + TB - 1) / TB, TB>>>(Nn, a_s2, a_d2);
  agg2_kernel<<<(Nn * 32 + TB - 1) / TB, TB>>>(Nn, b2, out);
}